// round 15
// baseline (speedup 1.0000x reference)
#include <cuda_runtime.h>
#include <cuda_bf16.h>
#include <cuda_fp16.h>
#include <cstdint>

#define NNODES 50000
#define NEDGES 800000
#define FIN 256
#define FOUT 256
#define HEADS 8
#define CH 32
#define NEG_SLOPE 0.2f
#define LN_EPS 1e-5f

// ---------------- scratch (static device globals) -----------------------------
__device__ __half g_hf[(size_t)NNODES * FOUT];   // h in fp16, 25.6 MB
__device__ __nv_bfloat16 g_wh[FOUT * FIN];       // Wt hi: [n][k]
__device__ __nv_bfloat16 g_wl[FOUT * FIN];       // Wt lo: [n][k]
__device__ float g_asrc[NNODES * HEADS];
__device__ float g_adst[NNODES * HEADS];
__device__ int   g_cnt[NNODES];
__device__ int   g_off[NNODES + 1];
__device__ int   g_cur[NNODES];
__device__ int   g_col[NEDGES];
__device__ int   g_bsum[256];
__device__ int   g_is64;

__device__ __forceinline__ float leaky(float v) {
    return v > 0.f ? v : NEG_SLOPE * v;
}

__device__ __forceinline__ uint32_t smem_u32(const void* p) {
    uint32_t a;
    asm("{ .reg .u64 t; cvta.to.shared.u64 t, %1; cvt.u32.u64 %0, t; }"
        : "=r"(a) : "l"(p));
    return a;
}

// ---------------- int64/int32 edge-index detection ----------------------------
__global__ void detect_idx_kernel(const long long* __restrict__ ei, int n, int cnt) {
    if (threadIdx.x == 0 && blockIdx.x == 0) {
        int ok = 1;
        for (int i = 0; i < cnt; ++i) {
            long long v = ei[i];
            if (v < 0 || v >= (long long)n) { ok = 0; break; }
        }
        g_is64 = ok;
    }
}

__device__ __forceinline__ void load_edge(const void* eidx, int e, int i,
                                          int& src, int& dst) {
    if (g_is64) {
        const long long* p = (const long long*)eidx;
        src = (int)p[i];
        dst = (int)p[(size_t)e + i];
    } else {
        const int* p = (const int*)eidx;
        src = p[i];
        dst = p[e + i];
    }
}

// ---------------- W conversion: fp32 -> bf16 hi/lo transposed -----------------
__global__ void wconv_kernel(const float* __restrict__ W) {
    int idx = blockIdx.x * blockDim.x + threadIdx.x;
    if (idx < FOUT * FIN) {
        int nn = idx >> 8;     // out channel
        int k = idx & 255;     // in channel
        float w = W[k * FOUT + nn];
        __nv_bfloat16 hi = __float2bfloat16(w);
        __nv_bfloat16 lo = __float2bfloat16(w - __bfloat162float(hi));
        g_wh[nn * FIN + k] = hi;
        g_wl[nn * FIN + k] = lo;
    }
}

__global__ void zero_cnt_kernel(int n) {
    int i = blockIdx.x * blockDim.x + threadIdx.x;
    if (i < n) g_cnt[i] = 0;
}

// pack 8 fp32 -> uint4 of 8 bf16 (hi part, or residual-lo part)
__device__ __forceinline__ uint4 cvt8_bf16(float4 v0, float4 v1, bool lo) {
    float f[8] = {v0.x, v0.y, v0.z, v0.w, v1.x, v1.y, v1.z, v1.w};
    unsigned r[4];
#pragma unroll
    for (int i = 0; i < 4; ++i) {
        float fa = f[2 * i], fb = f[2 * i + 1];
        __nv_bfloat16 ha = __float2bfloat16(fa);
        __nv_bfloat16 hb = __float2bfloat16(fb);
        if (lo) {
            ha = __float2bfloat16(fa - __bfloat162float(ha));
            hb = __float2bfloat16(fb - __bfloat162float(hb));
        }
        __nv_bfloat162 t = __nv_bfloat162(ha, hb);
        r[i] = *reinterpret_cast<unsigned*>(&t);
    }
    return make_uint4(r[0], r[1], r[2], r[3]);
}

// ---------------- K1: double-buffered bf16 mma GEMM + fused conv + logits ------
// h = xh@Wh + xl@Wh + xh@Wl ; CTA 128x128; h stored fp16;
// per-head att logits fused in epilogue
#define APITCH 40
#define NITER 24
__global__ __launch_bounds__(256) void gemm_mma_kernel(const float* __restrict__ x,
                                                       const float* __restrict__ att_src,
                                                       const float* __restrict__ att_dst,
                                                       int M) {
    __shared__ __nv_bfloat16 As[2][128][APITCH];
    __shared__ __nv_bfloat16 Bs[2][128][APITCH];

    const int tid = threadIdx.x;
    const int warp = tid >> 5;
    const int lane = tid & 31;
    const int wm = warp & 1;
    const int wn = warp >> 1;
    const int m0 = blockIdx.x * 128;
    const int n0 = blockIdx.y * 128;

    float acc[4][4][4];
#pragma unroll
    for (int a = 0; a < 4; ++a)
#pragma unroll
        for (int b = 0; b < 4; ++b)
#pragma unroll
            for (int c = 0; c < 4; ++c) acc[a][b][c] = 0.f;

    const int lrow = tid >> 1;            // 0..127
    const int lk = (tid & 1) * 16;        // 0 or 16

    const int arow = wm * 64 + (lane & 7) + ((lane >> 3) & 1) * 8;
    const int acol = (lane >> 4) * 8;
    const int l16 = lane & 15;
    const int brow = wn * 32 + (l16 & 7);
    const int bcol = ((l16 >> 3) & 1) * 8;

    const int gr = m0 + lrow;
    const bool rok = gr < M;

    // it in [0,24): term t=it/8 (0: xh*Wh, 1: xl*Wh, 2: xh*Wl), kchunk=(it%8)*32
    auto load_tiles = [&](int it, uint4& a0, uint4& a1, uint4& b0, uint4& b1) {
        const int t = it >> 3;
        const int kc = (it & 7) << 5;
        const bool alo = (t == 1);
        const __nv_bfloat16* Bg = (t == 2) ? g_wl : g_wh;
        if (rok) {
            const float* ap = x + (size_t)gr * FIN + kc + lk;
            float4 v0 = __ldg((const float4*)ap);
            float4 v1 = __ldg((const float4*)(ap + 4));
            float4 v2 = __ldg((const float4*)(ap + 8));
            float4 v3 = __ldg((const float4*)(ap + 12));
            a0 = cvt8_bf16(v0, v1, alo);
            a1 = cvt8_bf16(v2, v3, alo);
        } else {
            a0 = make_uint4(0, 0, 0, 0);
            a1 = make_uint4(0, 0, 0, 0);
        }
        const __nv_bfloat16* bp = Bg + (size_t)(n0 + lrow) * FIN + kc + lk;
        b0 = *(const uint4*)bp;
        b1 = *(const uint4*)(bp + 8);
    };

    {
        uint4 a0, a1, b0, b1;
        load_tiles(0, a0, a1, b0, b1);
        *(uint4*)&As[0][lrow][lk]     = a0;
        *(uint4*)&As[0][lrow][lk + 8] = a1;
        *(uint4*)&Bs[0][lrow][lk]     = b0;
        *(uint4*)&Bs[0][lrow][lk + 8] = b1;
    }
    __syncthreads();

    for (int it = 0; it < NITER; ++it) {
        const int cur = it & 1;
        const int nxt = cur ^ 1;
        const bool more = (it + 1 < NITER);
        uint4 pa0, pa1, pb0, pb1;
        if (more) load_tiles(it + 1, pa0, pa1, pb0, pb1);

#pragma unroll
        for (int ks = 0; ks < 32; ks += 16) {
            uint32_t a[4][4];
#pragma unroll
            for (int mf = 0; mf < 4; ++mf) {
                uint32_t ad = smem_u32(&As[cur][arow + mf * 16][ks + acol]);
                asm volatile(
                    "ldmatrix.sync.aligned.m8n8.x4.shared.b16 {%0,%1,%2,%3}, [%4];"
                    : "=r"(a[mf][0]), "=r"(a[mf][1]), "=r"(a[mf][2]), "=r"(a[mf][3])
                    : "r"(ad));
            }
            uint32_t b[4][2];
#pragma unroll
            for (int nf = 0; nf < 4; ++nf) {
                uint32_t bd = smem_u32(&Bs[cur][brow + nf * 8][ks + bcol]);
                asm volatile(
                    "ldmatrix.sync.aligned.m8n8.x2.shared.b16 {%0,%1}, [%2];"
                    : "=r"(b[nf][0]), "=r"(b[nf][1]) : "r"(bd));
            }
#pragma unroll
            for (int mf = 0; mf < 4; ++mf)
#pragma unroll
                for (int nf = 0; nf < 4; ++nf) {
                    asm volatile(
                        "mma.sync.aligned.m16n8k16.row.col.f32.bf16.bf16.f32 "
                        "{%0,%1,%2,%3}, {%4,%5,%6,%7}, {%8,%9}, {%0,%1,%2,%3};"
                        : "+f"(acc[mf][nf][0]), "+f"(acc[mf][nf][1]),
                          "+f"(acc[mf][nf][2]), "+f"(acc[mf][nf][3])
                        : "r"(a[mf][0]), "r"(a[mf][1]), "r"(a[mf][2]), "r"(a[mf][3]),
                          "r"(b[nf][0]), "r"(b[nf][1]));
                }
        }

        if (more) {
            *(uint4*)&As[nxt][lrow][lk]     = pa0;
            *(uint4*)&As[nxt][lrow][lk + 8] = pa1;
            *(uint4*)&Bs[nxt][lrow][lk]     = pb0;
            *(uint4*)&Bs[nxt][lrow][lk + 8] = pb1;
        }
        __syncthreads();
    }

    // ---- epilogue: store h (fp16) + fused per-head attention logits ----
    const int rbase = m0 + wm * 64 + (lane >> 2);
    const int cbase = n0 + wn * 32 + (lane & 3) * 2;
    const int head = (n0 >> 5) + wn;   // warp's 32-col span = exactly one head

    float asv[8], adv[8];
#pragma unroll
    for (int nf = 0; nf < 4; ++nf)
#pragma unroll
        for (int t = 0; t < 2; ++t) {
            int c = (lane & 3) * 2 + nf * 8 + t;
            asv[nf * 2 + t] = __ldg(att_src + head * CH + c);
            adv[nf * 2 + t] = __ldg(att_dst + head * CH + c);
        }

#pragma unroll
    for (int mf = 0; mf < 4; ++mf) {
#pragma unroll
        for (int sub = 0; sub < 2; ++sub) {
            int r = rbase + mf * 16 + sub * 8;
            float ds = 0.f, dd = 0.f;
#pragma unroll
            for (int nf = 0; nf < 4; ++nf) {
                float v0 = acc[mf][nf][sub * 2 + 0];
                float v1 = acc[mf][nf][sub * 2 + 1];
                if (r < M) {
                    __half2 hv = __floats2half2_rn(v0, v1);
                    *(__half2*)(g_hf + (size_t)r * FOUT + cbase + nf * 8) = hv;
                }
                ds += v0 * asv[nf * 2] + v1 * asv[nf * 2 + 1];
                dd += v0 * adv[nf * 2] + v1 * adv[nf * 2 + 1];
            }
            ds += __shfl_xor_sync(0xffffffffu, ds, 1);
            ds += __shfl_xor_sync(0xffffffffu, ds, 2);
            dd += __shfl_xor_sync(0xffffffffu, dd, 1);
            dd += __shfl_xor_sync(0xffffffffu, dd, 2);
            if ((lane & 3) == 0 && r < M) {
                g_asrc[r * HEADS + head] = ds;
                g_adst[r * HEADS + head] = dd;
            }
        }
    }
}

// ---------------- CSR build ----------------------------------------------------
__global__ void count_kernel(const void* __restrict__ eidx, int e) {
    int i = blockIdx.x * blockDim.x + threadIdx.x;
    if (i >= e) return;
    int dst;
    if (g_is64) dst = (int)((const long long*)eidx)[(size_t)e + i];
    else        dst = ((const int*)eidx)[e + i];
    atomicAdd(&g_cnt[dst], 1);
}

__global__ __launch_bounds__(256) void scan1_kernel(int n) {
    __shared__ int sh[256];
    int i = blockIdx.x * 256 + threadIdx.x;
    sh[threadIdx.x] = (i < n) ? g_cnt[i] : 0;
    __syncthreads();
    for (int o = 128; o; o >>= 1) {
        if (threadIdx.x < o) sh[threadIdx.x] += sh[threadIdx.x + o];
        __syncthreads();
    }
    if (threadIdx.x == 0) g_bsum[blockIdx.x] = sh[0];
}

__global__ __launch_bounds__(256) void scan2_kernel(int nb, int n) {
    __shared__ int sh[256];
    int t = threadIdx.x;
    sh[t] = (t < nb) ? g_bsum[t] : 0;
    __syncthreads();
    for (int o = 1; o < 256; o <<= 1) {
        int v = (t >= o) ? sh[t - o] : 0;
        __syncthreads();
        sh[t] += v;
        __syncthreads();
    }
    if (t < nb) g_bsum[t] = sh[t];       // inclusive
    if (t == 255) g_off[n] = sh[nb - 1];
}

__global__ __launch_bounds__(256) void scan3_kernel(int n) {
    __shared__ int sh[256];
    int t = threadIdx.x;
    int i = blockIdx.x * 256 + t;
    int v = (i < n) ? g_cnt[i] : 0;
    sh[t] = v;
    __syncthreads();
    for (int o = 1; o < 256; o <<= 1) {
        int u = (t >= o) ? sh[t - o] : 0;
        __syncthreads();
        sh[t] += u;
        __syncthreads();
    }
    int bex = (blockIdx.x > 0) ? g_bsum[blockIdx.x - 1] : 0;
    if (i < n) {
        int off = bex + sh[t] - v;   // exclusive
        g_off[i] = off;
        g_cur[i] = off;
    }
}

__global__ void fill_kernel(const void* __restrict__ eidx, int e) {
    int i = blockIdx.x * blockDim.x + threadIdx.x;
    if (i >= e) return;
    int src, dst;
    load_edge(eidx, e, i, src, dst);
    int pos = atomicAdd(&g_cur[dst], 1);
    g_col[pos] = src;
}

// unpack 8 fp16 -> two float4
__device__ __forceinline__ void h8_to_f(uint4 hv, float4& f0, float4& f1) {
    const __half2* hp = (const __half2*)&hv;
    float2 a = __half22float2(hp[0]);
    float2 b = __half22float2(hp[1]);
    float2 c = __half22float2(hp[2]);
    float2 d = __half22float2(hp[3]);
    f0 = make_float4(a.x, a.y, b.x, b.y);
    f1 = make_float4(c.x, c.y, d.x, d.y);
}

// accumulate one edge: fetch weight for my head, fma 8 channels
__device__ __forceinline__ void acc_edge(float wgt, uint4 hv, int myhead,
                                         float4& acc0, float4& acc1) {
    float av = __shfl_sync(0xffffffffu, wgt, myhead);
    float4 f0, f1;
    h8_to_f(hv, f0, f1);
    acc0.x += f0.x * av; acc0.y += f0.y * av;
    acc0.z += f0.z * av; acc0.w += f0.w * av;
    acc1.x += f1.x * av; acc1.y += f1.y * av;
    acc1.z += f1.z * av; acc1.w += f1.w * av;
}

// -------- single-pass aggregate: unnormalized numerator + denominator fused ---
// 8-way unrolled main loop: batch all loads before any math for max MLP
__global__ __launch_bounds__(256) void aggregate_kernel(float* __restrict__ out,
                                                        const float* __restrict__ bias,
                                                        const float* __restrict__ gamma,
                                                        const float* __restrict__ beta,
                                                        int n) {
    int d = (blockIdx.x * blockDim.x + threadIdx.x) >> 5;
    int lane = threadIdx.x & 31;
    if (d >= n) return;

    const int off = g_off[d];
    const int deg = g_off[d + 1] - off;

    float4 t0 = *(const float4*)(g_adst + d * HEADS);
    float4 t1 = *(const float4*)(g_adst + d * HEADS + 4);
    float adst8[8] = {t0.x, t0.y, t0.z, t0.w, t1.x, t1.y, t1.z, t1.w};
    float4 u0 = *(const float4*)(g_asrc + d * HEADS);
    float4 u1 = *(const float4*)(g_asrc + d * HEADS + 4);
    float asd[8] = {u0.x, u0.y, u0.z, u0.w, u1.x, u1.y, u1.z, u1.w};

    const int lk = lane & 7;        // head this lane evaluates weights for
    const int myhead = lane >> 2;   // head owning this lane's 8 output channels
    float adst_lk = 0.f, asd_lk = 0.f;
#pragma unroll
    for (int k = 0; k < 8; ++k)
        if (lk == k) { adst_lk = adst8[k]; asd_lk = asd[k]; }

    // self-loop: weight for head lk; numerator seeded with myhead's self weight
    float sw = __expf(leaky(asd_lk + adst_lk));
    float ws_my = __shfl_sync(0xffffffffu, sw, myhead);

    uint4 shv = __ldg((const uint4*)(g_hf + (size_t)d * FOUT + lane * 8));
    float4 v0, v1;
    h8_to_f(shv, v0, v1);
    float4 acc0 = make_float4(v0.x * ws_my, v0.y * ws_my, v0.z * ws_my, v0.w * ws_my);
    float4 acc1 = make_float4(v1.x * ws_my, v1.y * ws_my, v1.z * ws_my, v1.w * ws_my);

    int j = 0;
    for (; j + 8 <= deg; j += 8) {
        int ss[8];
#pragma unroll
        for (int q = 0; q < 8; ++q) ss[q] = __ldg(g_col + off + j + q);
        float aa[8];
#pragma unroll
        for (int q = 0; q < 8; ++q) aa[q] = __ldg(g_asrc + ss[q] * HEADS + lk);
        uint4 hv[8];
#pragma unroll
        for (int q = 0; q < 8; ++q)
            hv[q] = __ldg((const uint4*)(g_hf + (size_t)ss[q] * FOUT + lane * 8));
        float w[8];
#pragma unroll
        for (int q = 0; q < 8; ++q) {
            w[q] = __expf(leaky(aa[q] + adst_lk));
            sw += w[q];
        }
#pragma unroll
        for (int q = 0; q < 8; ++q) acc_edge(w[q], hv[q], myhead, acc0, acc1);
    }
    for (; j + 4 <= deg; j += 4) {
        int ss[4];
#pragma unroll
        for (int q = 0; q < 4; ++q) ss[q] = __ldg(g_col + off + j + q);
        float aa[4];
#pragma unroll
        for (int q = 0; q < 4; ++q) aa[q] = __ldg(g_asrc + ss[q] * HEADS + lk);
        uint4 hv[4];
#pragma unroll
        for (int q = 0; q < 4; ++q)
            hv[q] = __ldg((const uint4*)(g_hf + (size_t)ss[q] * FOUT + lane * 8));
#pragma unroll
        for (int q = 0; q < 4; ++q) {
            float w = __expf(leaky(aa[q] + adst_lk));
            sw += w;
            acc_edge(w, hv[q], myhead, acc0, acc1);
        }
    }
    for (; j < deg; ++j) {
        int s0 = __ldg(g_col + off + j);
        float a0 = __ldg(g_asrc + s0 * HEADS + lk);
        uint4 hv0 = __ldg((const uint4*)(g_hf + (size_t)s0 * FOUT + lane * 8));
        float w0 = __expf(leaky(a0 + adst_lk));
        sw += w0;
        acc_edge(w0, hv0, myhead, acc0, acc1);
    }

    // normalize by my head's denominator
    float dsum = __shfl_sync(0xffffffffu, sw, myhead);
    float rin = 1.f / dsum;
    acc0.x *= rin; acc0.y *= rin; acc0.z *= rin; acc0.w *= rin;
    acc1.x *= rin; acc1.y *= rin; acc1.z *= rin; acc1.w *= rin;

    // ---- bias + LayerNorm + ReLU ----
    const int c0 = lane * 8;
    float4 b0 = *(const float4*)(bias + c0);
    float4 b1 = *(const float4*)(bias + c0 + 4);
    acc0.x += b0.x; acc0.y += b0.y; acc0.z += b0.z; acc0.w += b0.w;
    acc1.x += b1.x; acc1.y += b1.y; acc1.z += b1.z; acc1.w += b1.w;

    float s = acc0.x + acc0.y + acc0.z + acc0.w + acc1.x + acc1.y + acc1.z + acc1.w;
    float q = acc0.x * acc0.x + acc0.y * acc0.y + acc0.z * acc0.z + acc0.w * acc0.w +
              acc1.x * acc1.x + acc1.y * acc1.y + acc1.z * acc1.z + acc1.w * acc1.w;
#pragma unroll
    for (int o = 16; o; o >>= 1) {
        s += __shfl_xor_sync(0xffffffffu, s, o);
        q += __shfl_xor_sync(0xffffffffu, q, o);
    }
    float mu = s * (1.f / FOUT);
    float var = q * (1.f / FOUT) - mu * mu;
    float rs = rsqrtf(var + LN_EPS);

    float4 g0 = *(const float4*)(gamma + c0);
    float4 g1 = *(const float4*)(gamma + c0 + 4);
    float4 e0 = *(const float4*)(beta + c0);
    float4 e1 = *(const float4*)(beta + c0 + 4);
    float4 r0, r1;
    r0.x = fmaxf((acc0.x - mu) * rs * g0.x + e0.x, 0.f);
    r0.y = fmaxf((acc0.y - mu) * rs * g0.y + e0.y, 0.f);
    r0.z = fmaxf((acc0.z - mu) * rs * g0.z + e0.z, 0.f);
    r0.w = fmaxf((acc0.w - mu) * rs * g0.w + e0.w, 0.f);
    r1.x = fmaxf((acc1.x - mu) * rs * g1.x + e1.x, 0.f);
    r1.y = fmaxf((acc1.y - mu) * rs * g1.y + e1.y, 0.f);
    r1.z = fmaxf((acc1.z - mu) * rs * g1.z + e1.z, 0.f);
    r1.w = fmaxf((acc1.w - mu) * rs * g1.w + e1.w, 0.f);
    float* row = out + (size_t)d * FOUT + c0;
    *(float4*)row       = r0;
    *(float4*)(row + 4) = r1;
}

// ---------------- launch: fork CSR chain onto side stream ---------------------
extern "C" void kernel_launch(void* const* d_in, const int* in_sizes, int n_in,
                              void* d_out, int out_size) {
    const float* x       = (const float*)d_in[0];
    const void*  eidx    = d_in[1];
    const float* W       = (const float*)d_in[2];
    const float* att_src = (const float*)d_in[3];
    const float* att_dst = (const float*)d_in[4];
    const float* bias    = (const float*)d_in[5];
    const float* gamma   = (const float*)d_in[6];
    const float* beta    = (const float*)d_in[7];
    float* out = (float*)d_out;

    const int n = in_sizes[0] / FIN;     // 50000
    const int e = in_sizes[1] / 2;       // 800000

    // lazily created on first (non-captured) call; reused by capture
    static cudaStream_t s2 = nullptr;
    static cudaEvent_t evF = nullptr, evJ = nullptr;
    if (s2 == nullptr) {
        cudaStreamCreateWithFlags(&s2, cudaStreamNonBlocking);
        cudaEventCreateWithFlags(&evF, cudaEventDisableTiming);
        cudaEventCreateWithFlags(&evJ, cudaEventDisableTiming);
    }

    int cnt = 64 < 2 * e ? 64 : 2 * e;
    detect_idx_kernel<<<1, 32>>>((const long long*)eidx, n, cnt);

    // fork: CSR chain on s2 (depends only on eidx + g_is64)
    cudaEventRecord(evF, 0);
    cudaStreamWaitEvent(s2, evF, 0);

    const int nb = (n + 255) / 256;      // 196
    zero_cnt_kernel<<<nb, 256, 0, s2>>>(n);
    count_kernel<<<(e + 255) / 256, 256, 0, s2>>>(eidx, e);
    scan1_kernel<<<nb, 256, 0, s2>>>(n);
    scan2_kernel<<<1, 256, 0, s2>>>(nb, n);
    scan3_kernel<<<nb, 256, 0, s2>>>(n);
    fill_kernel<<<(e + 255) / 256, 256, 0, s2>>>(eidx, e);
    cudaEventRecord(evJ, s2);

    // main stream: W conversion + GEMM (independent of CSR)
    wconv_kernel<<<(FOUT * FIN + 255) / 256, 256>>>(W);
    dim3 ggrid((n + 127) / 128, FOUT / 128);
    gemm_mma_kernel<<<ggrid, 256>>>(x, att_src, att_dst, n);

    // join, then aggregate (needs h/asrc/adst AND CSR)
    cudaStreamWaitEvent(0, evJ, 0);
    aggregate_kernel<<<(n * 32 + 255) / 256, 256>>>(out, bias, gamma, beta, n);
}